// round 1
// baseline (speedup 1.0000x reference)
#include <cuda_runtime.h>

#define Tn 128
#define Bn 8
#define En 256
#define Hn 512
#define G4 2048
#define NB2 128
#define NT2 128
#define WSTR 516   // 512 + pad(4) -> 16B aligned rows, conflict-minimal

// ---------------- device scratch (no runtime allocation allowed) ----------------
__device__ float g_xs[Tn * Bn * G4];   // emb@Wih_s + b_s, layout [(t*8+b)*2048 + col]
__device__ float g_xt[Tn * Bn * G4];   // emb@Wih_t + b_t
__device__ float g_h[2][Bn * Hn];      // double-buffered recurrent state
__device__ unsigned int g_cnt;         // barrier arrive counter (self-resetting)
__device__ unsigned int g_gen;         // barrier generation (monotonic)

// ---------------- helpers ----------------
__device__ __forceinline__ unsigned long long fma2(unsigned long long a,
                                                   unsigned long long b,
                                                   unsigned long long c) {
    unsigned long long d;
    asm("fma.rn.f32x2 %0, %1, %2, %3;" : "=l"(d) : "l"(a), "l"(b), "l"(c));
    return d;
}
__device__ __forceinline__ float2 up2(unsigned long long a) {
    float2 f;
    asm("mov.b64 {%0, %1}, %2;" : "=f"(f.x), "=f"(f.y) : "l"(a));
    return f;
}
__device__ __forceinline__ float sigm(float x) { return 1.f / (1.f + expf(-x)); }

// ---------------- kernel 1: gathered input GEMM (emb @ Wih + bias) ----------------
// M=1024 (rows = t*8+b), N=2048, K=256. BM=BN=128, BK=16, 256 threads, 8x8/thread.
__global__ void __launch_bounds__(256) input_gemm(const int* __restrict__ tokens,
                                                  const float* __restrict__ etab,
                                                  const float* __restrict__ W,
                                                  const float* __restrict__ bias,
                                                  int which) {
    __shared__ float As[16][128];
    __shared__ float Bs[16][128];
    float* outp = which ? g_xt : g_xs;

    const int m0 = blockIdx.y * 128;
    const int n0 = blockIdx.x * 128;
    const int tid = threadIdx.x;
    const int tr = tid >> 4, tc = tid & 15;

    float acc[8][8];
#pragma unroll
    for (int i = 0; i < 8; i++)
#pragma unroll
        for (int j = 0; j < 8; j++) acc[i][j] = 0.f;

    // A-load mapping: idx -> (m = idx>>2, kq = idx&3), two passes of 256
    const int mA0 = tid >> 2;            // 0..63
    const int mA1 = (tid + 256) >> 2;    // 64..127
    const int kq0 = tid & 3;
    const int gm0 = m0 + mA0, gm1 = m0 + mA1;
    const long tok0 = tokens[(gm0 & 7) * Tn + (gm0 >> 3)];
    const long tok1 = tokens[(gm1 & 7) * Tn + (gm1 >> 3)];

    const int kb = tid >> 5;   // 0..7
    const int nq = tid & 31;   // 0..31

    for (int k0 = 0; k0 < En; k0 += 16) {
        float4 a0 = *(const float4*)&etab[tok0 * En + k0 + kq0 * 4];
        float4 a1 = *(const float4*)&etab[tok1 * En + k0 + kq0 * 4];
        As[kq0 * 4 + 0][mA0] = a0.x; As[kq0 * 4 + 1][mA0] = a0.y;
        As[kq0 * 4 + 2][mA0] = a0.z; As[kq0 * 4 + 3][mA0] = a0.w;
        As[kq0 * 4 + 0][mA1] = a1.x; As[kq0 * 4 + 1][mA1] = a1.y;
        As[kq0 * 4 + 2][mA1] = a1.z; As[kq0 * 4 + 3][mA1] = a1.w;

        *(float4*)&Bs[kb][nq * 4]     = *(const float4*)&W[(k0 + kb) * G4 + n0 + nq * 4];
        *(float4*)&Bs[kb + 8][nq * 4] = *(const float4*)&W[(k0 + kb + 8) * G4 + n0 + nq * 4];
        __syncthreads();

#pragma unroll
        for (int k = 0; k < 16; k++) {
            float av[8], bv[8];
            *(float4*)&av[0] = *(const float4*)&As[k][tr * 4];
            *(float4*)&av[4] = *(const float4*)&As[k][64 + tr * 4];
            *(float4*)&bv[0] = *(const float4*)&Bs[k][tc * 4];
            *(float4*)&bv[4] = *(const float4*)&Bs[k][64 + tc * 4];
#pragma unroll
            for (int i = 0; i < 8; i++)
#pragma unroll
                for (int j = 0; j < 8; j++) acc[i][j] += av[i] * bv[j];
        }
        __syncthreads();
    }

#pragma unroll
    for (int i = 0; i < 8; i++) {
        int m = m0 + ((i < 4) ? (tr * 4 + i) : (64 + tr * 4 + i - 4));
#pragma unroll
        for (int jh = 0; jh < 2; jh++) {
            int n = n0 + tc * 4 + jh * 64;
            float4 v;
            v.x = acc[i][jh * 4 + 0] + __ldg(&bias[n + 0]);
            v.y = acc[i][jh * 4 + 1] + __ldg(&bias[n + 1]);
            v.z = acc[i][jh * 4 + 2] + __ldg(&bias[n + 2]);
            v.w = acc[i][jh * 4 + 3] + __ldg(&bias[n + 3]);
            *(float4*)&outp[(long)m * G4 + n] = v;
        }
    }
}

// ---------------- kernel 2: persistent dual-LSTM ----------------
// 128 blocks x 128 threads. Block bl owns h-units [bl*4, bl*4+4) => 16 gate cols.
// thread: c = tid&15 (gate-col within block), b = tid>>4 (batch).
__global__ void __launch_bounds__(NT2) lstm_kernel(const float* __restrict__ Whh_s,
                                                   const float* __restrict__ Whh_t,
                                                   const float* __restrict__ Wmh_t,
                                                   float* __restrict__ out) {
    extern __shared__ float sm[];
    float* ws  = sm;                 // [16][WSTR] Whh_s slice, col-major per column
    float* wt  = ws + 16 * WSTR;     // [16][WSTR] Whh_t slice
    float* hs  = wt + 16 * WSTR;     // [8][WSTR]  current h
    float* pre = hs + 8 * WSTR;      // [16][8]    pre-activations, pre[c*8+b]
    float* cst = pre + 128;          // [32]       c-state (b*4 + j)
    float* rcs = cst + 32;           // [16][8]    h_last @ Wmh_t slice

    const int tid = threadIdx.x;
    const int bl  = blockIdx.x;
    const int c   = tid & 15;
    const int b   = tid >> 4;
    const int col = (c >> 2) * Hn + bl * 4 + (c & 3);

    // load weight slices (one-time)
    for (int i = tid; i < 16 * Hn; i += NT2) {
        int cc = i & 15, k = i >> 4;
        int cl = (cc >> 2) * Hn + bl * 4 + (cc & 3);
        ws[cc * WSTR + k] = Whh_s[(long)k * G4 + cl];
        wt[cc * WSTR + k] = Whh_t[(long)k * G4 + cl];
    }
    if (tid < 32) {
        int bb = tid >> 2, j = tid & 3;
        __stcg(&g_h[0][bb * Hn + bl * 4 + j], 0.f);
        cst[tid] = 0.f;
    }

    unsigned base_gen = 0;
    if (tid == 0) base_gen = *(volatile unsigned int*)&g_gen;
    int nbar = 0;

    auto gbar = [&]() {
        __syncthreads();
        if (tid == 0) {
            nbar++;
            __threadfence();
            unsigned old = atomicAdd(&g_cnt, 1u);
            if (old == (unsigned)(NB2 - 1)) {
                g_cnt = 0u;
                __threadfence();
                atomicAdd(&g_gen, 1u);
            } else {
                while ((*(volatile unsigned int*)&g_gen) - base_gen < (unsigned)nbar) {}
            }
            __threadfence();
        }
        __syncthreads();
    };

    auto load_h = [&](int rp) {
#pragma unroll
        for (int i = 0; i < 8; i++) {
            int idx = tid + i * NT2;          // 0..1023
            int bb = idx >> 7, k4 = idx & 127;
            float4 v = __ldcg((const float4*)&g_h[rp][bb * Hn + k4 * 4]);
            *(float4*)&hs[bb * WSTR + k4 * 4] = v;
        }
    };

    auto do_step = [&](const float* wsel, const float* xbase, const float* rcp,
                       int t, int rp, int wp, float* outp) {
        load_h(rp);
        float xval = __ldg(&xbase[(long)(t * Bn + b) * G4 + col]);
        if (rcp) xval += rcp[c * 8 + b];
        __syncthreads();

        const float* hrow = hs + b * WSTR;
        const float* wrow = wsel + c * WSTR;
        unsigned long long acc0 = 0ull, acc1 = 0ull;
#pragma unroll 8
        for (int kq = 0; kq < Hn / 4; kq++) {
            ulonglong2 hv = *(const ulonglong2*)(hrow + kq * 4);
            ulonglong2 wv = *(const ulonglong2*)(wrow + kq * 4);
            acc0 = fma2(hv.x, wv.x, acc0);
            acc1 = fma2(hv.y, wv.y, acc1);
        }
        float2 f0 = up2(acc0), f1 = up2(acc1);
        pre[c * 8 + b] = xval + (f0.x + f1.x) + (f0.y + f1.y);
        __syncthreads();

        if (tid < 32) {
            int bb = tid >> 2, j = tid & 3;
            float iv = pre[(0  + j) * 8 + bb];
            float fv = pre[(4  + j) * 8 + bb];
            float gv = pre[(8  + j) * 8 + bb];
            float ov = pre[(12 + j) * 8 + bb];
            float cn = sigm(fv) * cst[tid] + sigm(iv) * tanhf(gv);
            float hn = sigm(ov) * tanhf(cn);
            cst[tid] = cn;
            __stcg(&g_h[wp][bb * Hn + bl * 4 + j], hn);
            if (outp) outp[(long)(bb * Tn + t) * Hn + bl * 4 + j] = hn;
        }
        gbar();
    };

    gbar();  // barrier 1: h=0 visible everywhere

    // ---- shared LSTM (only h_last matters; attention is identity => Rt = h_last) ----
    for (int t = 0; t < Tn; t++)
        do_step(ws, g_xs, nullptr, t, t & 1, (t & 1) ^ 1, nullptr);

    // h_last now in g_h[0]; snapshot it, then reset state
    load_h(0);
    __syncthreads();
    gbar();  // all blocks hold h_last locally -> safe to overwrite g_h[0]

    if (tid < 32) {
        int bb = tid >> 2, j = tid & 3;
        __stcg(&g_h[0][bb * Hn + bl * 4 + j], 0.f);
        cst[tid] = 0.f;
    }
    // rc = h_last @ Wmh_t  (constant across task steps)
    {
        const float* hrow = hs + b * WSTR;
        float r = 0.f;
#pragma unroll 8
        for (int k = 0; k < Hn; k++)
            r += hrow[k] * __ldg(&Wmh_t[(long)k * G4 + col]);
        rcs[c * 8 + b] = r;
    }
    gbar();  // zeros + rcs published

    // ---- task LSTM, writing output ----
    for (int t = 0; t < Tn; t++)
        do_step(wt, g_xt, rcs, t, t & 1, (t & 1) ^ 1, out);
}

// ---------------- launch ----------------
extern "C" void kernel_launch(void* const* d_in, const int* in_sizes, int n_in,
                              void* d_out, int out_size) {
    // input order: tokens, TASK, embed_table, Wih_s, Whh_s, b_s, Ws_w, Ws_b,
    //              Us_w, Us_b, Wih_t, Whh_t, Wmh_t, b_t   (TASK may be absent)
    const int sh = (n_in == 14) ? 0 : 1;  // shift if TASK scalar was dropped
    const int*   tokens = (const int*)d_in[0];
    const float* etab   = (const float*)d_in[2 - sh];
    const float* Wih_s  = (const float*)d_in[3 - sh];
    const float* Whh_s  = (const float*)d_in[4 - sh];
    const float* b_s    = (const float*)d_in[5 - sh];
    const float* Wih_t  = (const float*)d_in[10 - sh];
    const float* Whh_t  = (const float*)d_in[11 - sh];
    const float* Wmh_t  = (const float*)d_in[12 - sh];
    const float* b_t    = (const float*)d_in[13 - sh];
    float* out = (float*)d_out;

    const int smem2 = (16 * WSTR * 2 + 8 * WSTR + 128 + 32 + 128) * (int)sizeof(float);
    cudaFuncSetAttribute(lstm_kernel, cudaFuncAttributeMaxDynamicSharedMemorySize, smem2);

    dim3 gg(G4 / 128, (Tn * Bn) / 128);  // (16, 8)
    input_gemm<<<gg, 256>>>(tokens, etab, Wih_s, b_s, 0);
    input_gemm<<<gg, 256>>>(tokens, etab, Wih_t, b_t, 1);
    lstm_kernel<<<NB2, NT2, smem2>>>(Whh_s, Whh_t, Wmh_t, out);
}